// round 8
// baseline (speedup 1.0000x reference)
#include <cuda_runtime.h>
#include <cuda_fp16.h>

#define NN 50000
#define EE 800000
#define NEG 0.2f
#define EPSV 1e-5f

// ---- scratch (static __device__, no allocations) ----
__device__ __half g_xlh[NN * 128];   // fp16 mirror: ONLY consumer of xl is the gather
__device__ float  g_xr[NN * 128];
__device__ float  g_y[NN * 64];
__device__ int    g_cnt[NN];
__device__ int    g_wofs[NN];
__device__ int    g_rowptr[NN + 1];
__device__ int    g_csrsrc[EE];
__device__ float  g_sum[64];
__device__ float  g_sumsq[64];
__device__ float  g_nA[64];
__device__ float  g_nB[64];

// 4 halves <-> float4 helpers
__device__ __forceinline__ float4 h4_to_f4(uint2 h) {
    float2 a = __half22float2(*reinterpret_cast<__half2*>(&h.x));
    float2 b = __half22float2(*reinterpret_cast<__half2*>(&h.y));
    return make_float4(a.x, a.y, b.x, b.y);
}
__device__ __forceinline__ uint2 f4_to_h4(float4 v) {
    __half2 a = __floats2half2_rn(v.x, v.y);
    __half2 b = __floats2half2_rn(v.z, v.w);
    uint2 r;
    r.x = *reinterpret_cast<unsigned*>(&a);
    r.y = *reinterpret_cast<unsigned*>(&b);
    return r;
}

// ---------------- CSR build ----------------
__global__ void k_zero_all() {
    int i = blockIdx.x * blockDim.x + threadIdx.x;
    if (i < NN) g_cnt[i] = 0;
    if (i < 64) { g_sum[i] = 0.f; g_sumsq[i] = 0.f; }
}

__global__ void k_hist(const int* __restrict__ dst) {
    int e = blockIdx.x * blockDim.x + threadIdx.x;
    if (e < EE) atomicAdd(&g_cnt[dst[e]], 1);
}

__global__ void k_scan() {
    __shared__ int sT[1024];
    int tid = threadIdx.x;
    const int CH = (NN + 1023) / 1024;
    int base = tid * CH;
    int s = 0;
    for (int i = 0; i < CH; i++) {
        int idx = base + i;
        s += (idx < NN) ? g_cnt[idx] : 0;
    }
    sT[tid] = s;
    __syncthreads();
    for (int off = 1; off < 1024; off <<= 1) {
        int v = (tid >= off) ? sT[tid - off] : 0;
        __syncthreads();
        sT[tid] += v;
        __syncthreads();
    }
    int run = (tid == 0) ? 0 : sT[tid - 1];
    for (int i = 0; i < CH; i++) {
        int idx = base + i;
        if (idx < NN) {
            g_rowptr[idx] = run;
            g_wofs[idx]   = run;
            run += g_cnt[idx];
        }
    }
    if (tid == 1023) g_rowptr[NN] = run;
}

__global__ void k_scatter(const int* __restrict__ src, const int* __restrict__ dst) {
    int e = blockIdx.x * blockDim.x + threadIdx.x;
    if (e < EE) {
        int p = atomicAdd(&g_wofs[dst[e]], 1);
        g_csrsrc[p] = src[e];
    }
}

// ---------------- layer-1 GEMM (din = 3) ----------------
__global__ void k_gemm3(const float* __restrict__ x,
                        const float* __restrict__ Wl,
                        const float* __restrict__ Wr) {
    int t = blockIdx.x * blockDim.x + threadIdx.x;
    int row = t >> 5, q = t & 31;
    if (row >= NN) return;
    float x0 = __ldg(&x[row * 3 + 0]);
    float x1 = __ldg(&x[row * 3 + 1]);
    float x2 = __ldg(&x[row * 3 + 2]);
    const float4* Wl4 = (const float4*)Wl;
    const float4* Wr4 = (const float4*)Wr;
    float4 a = __ldg(&Wl4[q]), b = __ldg(&Wl4[32 + q]), c = __ldg(&Wl4[64 + q]);
    float4 o;
    o.x = x0 * a.x + x1 * b.x + x2 * c.x;
    o.y = x0 * a.y + x1 * b.y + x2 * c.y;
    o.z = x0 * a.z + x1 * b.z + x2 * c.z;
    o.w = x0 * a.w + x1 * b.w + x2 * c.w;
    ((uint2*)g_xlh)[row * 32 + q] = f4_to_h4(o);   // fp16 xl
    a = __ldg(&Wr4[q]); b = __ldg(&Wr4[32 + q]); c = __ldg(&Wr4[64 + q]);
    o.x = x0 * a.x + x1 * b.x + x2 * c.x;
    o.y = x0 * a.y + x1 * b.y + x2 * c.y;
    o.z = x0 * a.z + x1 * b.z + x2 * c.z;
    o.w = x0 * a.w + x1 * b.w + x2 * c.w;
    ((float4*)g_xr)[row * 32 + q] = o;
}

// ---------------- layers 2/3 dual GEMM with fused GraphNorm+ReLU on input ----------------
// input row = relu(g_y * A + B);  xl(N,128,fp16) / xr(N,128,fp32) = in(N,64) @ W(64,128)
// grid (782, 4): by 0/1 -> Wl col-half 0/1 ; by 2/3 -> Wr col-half 0/1
__global__ void k_gemm64(const float* __restrict__ W_l, const float* __restrict__ W_r) {
    __shared__ float As[64][68];   // padded: conflict-free scalar reads
    __shared__ float Ws[64][64];
    int by = blockIdx.y;
    const float* W = (by < 2) ? W_l : W_r;
    int colbase = (by & 1) * 64;
    int row0 = blockIdx.x * 64;
    int tid = threadIdx.x;  // 256

    // A tile load with fused normalize + relu
    for (int i = tid; i < 64 * 16; i += 256) {
        int r = i >> 4, k4 = (i & 15) * 4;
        float4 v = make_float4(0.f, 0.f, 0.f, 0.f);
        if (row0 + r < NN) v = ((const float4*)g_y)[(row0 + r) * 16 + (k4 >> 2)];
        v.x = fmaxf(v.x * g_nA[k4 + 0] + g_nB[k4 + 0], 0.f);
        v.y = fmaxf(v.y * g_nA[k4 + 1] + g_nB[k4 + 1], 0.f);
        v.z = fmaxf(v.z * g_nA[k4 + 2] + g_nB[k4 + 2], 0.f);
        v.w = fmaxf(v.w * g_nA[k4 + 3] + g_nB[k4 + 3], 0.f);
        *(float4*)&As[r][k4] = v;
    }
    for (int i = tid; i < 64 * 16; i += 256) {
        int k = i >> 4, c4 = i & 15;
        *(float4*)&Ws[k][c4 * 4] = __ldg((const float4*)(W + k * 128 + colbase + c4 * 4));
    }
    __syncthreads();

    int tx = tid & 15, ty = tid >> 4;
    float acc[4][4];
#pragma unroll
    for (int i = 0; i < 4; i++)
#pragma unroll
        for (int j = 0; j < 4; j++) acc[i][j] = 0.f;

#pragma unroll 8
    for (int k = 0; k < 64; k++) {
        float4 wv = *(float4*)&Ws[k][tx * 4];
        float a0 = As[ty * 4 + 0][k];
        float a1 = As[ty * 4 + 1][k];
        float a2 = As[ty * 4 + 2][k];
        float a3 = As[ty * 4 + 3][k];
        acc[0][0] += a0 * wv.x; acc[0][1] += a0 * wv.y; acc[0][2] += a0 * wv.z; acc[0][3] += a0 * wv.w;
        acc[1][0] += a1 * wv.x; acc[1][1] += a1 * wv.y; acc[1][2] += a1 * wv.z; acc[1][3] += a1 * wv.w;
        acc[2][0] += a2 * wv.x; acc[2][1] += a2 * wv.y; acc[2][2] += a2 * wv.z; acc[2][3] += a2 * wv.w;
        acc[3][0] += a3 * wv.x; acc[3][1] += a3 * wv.y; acc[3][2] += a3 * wv.z; acc[3][3] += a3 * wv.w;
    }
#pragma unroll
    for (int i = 0; i < 4; i++) {
        int r = row0 + ty * 4 + i;
        if (r < NN) {
            float4 o = make_float4(acc[i][0], acc[i][1], acc[i][2], acc[i][3]);
            if (by < 2)
                ((uint2*)g_xlh)[r * 32 + (colbase >> 2) + tx] = f4_to_h4(o);
            else
                *(float4*)&g_xr[r * 128 + colbase + tx * 4] = o;
        }
    }
}

// ---- per-edge logit partial: leakyrelu + att dot ----
__device__ __forceinline__ float logit_part(float4 xlv, float4 xrv, float4 attv) {
    float cx = xlv.x + xrv.x, cy = xlv.y + xrv.y, cz = xlv.z + xrv.z, cw = xlv.w + xrv.w;
    cx = fmaxf(cx, NEG * cx); cy = fmaxf(cy, NEG * cy);
    cz = fmaxf(cz, NEG * cz); cw = fmaxf(cw, NEG * cw);
    return cx * attv.x + cy * attv.y + cz * attv.z + cw * attv.w;
}

// ---------------- aggregation: one warp per node, fp16 gather, 4 edges in flight ----------------
// lane l handles channels [l*4, l*4+4); lanes 0..15 = head 0, 16..31 = head 1.
__global__ void k_agg(const float* __restrict__ att, const float* __restrict__ bias) {
    __shared__ float ssum[64], ssq[64];
    int tid = threadIdx.x;
    if (tid < 64) { ssum[tid] = 0.f; ssq[tid] = 0.f; }
    __syncthreads();

    int v = (blockIdx.x * 256 + tid) >> 5;   // 6250 blocks * 8 warps = 50000 exactly
    int lane = tid & 31;
    const uint2* xlh = (const uint2*)g_xlh;
    float4 xrv  = ((const float4*)g_xr)[v * 32 + lane];
    float4 attv = __ldg(&((const float4*)att)[lane]);

    // self-loop: exp reference (a_self = 1)
    float4 xs = h4_to_f4(xlh[v * 32 + lane]);
    float m = logit_part(xs, xrv, attv);
    m += __shfl_xor_sync(0xffffffffu, m, 8);
    m += __shfl_xor_sync(0xffffffffu, m, 4);
    m += __shfl_xor_sync(0xffffffffu, m, 2);
    m += __shfl_xor_sync(0xffffffffu, m, 1);

    float z = 1.f;
    float4 acc = xs;

    int e0 = __ldg(&g_rowptr[v]);
    int e1 = __ldg(&g_rowptr[v + 1]);
    int e = e0;
    for (; e + 4 <= e1; e += 4) {
        int u0 = __ldg(&g_csrsrc[e]);
        int u1 = __ldg(&g_csrsrc[e + 1]);
        int u2 = __ldg(&g_csrsrc[e + 2]);
        int u3 = __ldg(&g_csrsrc[e + 3]);
        float4 x0 = h4_to_f4(__ldg(&xlh[u0 * 32 + lane]));
        float4 x1 = h4_to_f4(__ldg(&xlh[u1 * 32 + lane]));
        float4 x2 = h4_to_f4(__ldg(&xlh[u2 * 32 + lane]));
        float4 x3 = h4_to_f4(__ldg(&xlh[u3 * 32 + lane]));
        float p0 = logit_part(x0, xrv, attv);
        float p1 = logit_part(x1, xrv, attv);
        float p2 = logit_part(x2, xrv, attv);
        float p3 = logit_part(x3, xrv, attv);
        p0 += __shfl_xor_sync(0xffffffffu, p0, 8);
        p1 += __shfl_xor_sync(0xffffffffu, p1, 8);
        p2 += __shfl_xor_sync(0xffffffffu, p2, 8);
        p3 += __shfl_xor_sync(0xffffffffu, p3, 8);
        p0 += __shfl_xor_sync(0xffffffffu, p0, 4);
        p1 += __shfl_xor_sync(0xffffffffu, p1, 4);
        p2 += __shfl_xor_sync(0xffffffffu, p2, 4);
        p3 += __shfl_xor_sync(0xffffffffu, p3, 4);
        p0 += __shfl_xor_sync(0xffffffffu, p0, 2);
        p1 += __shfl_xor_sync(0xffffffffu, p1, 2);
        p2 += __shfl_xor_sync(0xffffffffu, p2, 2);
        p3 += __shfl_xor_sync(0xffffffffu, p3, 2);
        p0 += __shfl_xor_sync(0xffffffffu, p0, 1);
        p1 += __shfl_xor_sync(0xffffffffu, p1, 1);
        p2 += __shfl_xor_sync(0xffffffffu, p2, 1);
        p3 += __shfl_xor_sync(0xffffffffu, p3, 1);
        float a0 = __expf(p0 - m);
        float a1 = __expf(p1 - m);
        float a2 = __expf(p2 - m);
        float a3 = __expf(p3 - m);
        z += (a0 + a1) + (a2 + a3);
        acc.x += a0 * x0.x + a1 * x1.x + a2 * x2.x + a3 * x3.x;
        acc.y += a0 * x0.y + a1 * x1.y + a2 * x2.y + a3 * x3.y;
        acc.z += a0 * x0.z + a1 * x1.z + a2 * x2.z + a3 * x3.z;
        acc.w += a0 * x0.w + a1 * x1.w + a2 * x2.w + a3 * x3.w;
    }
    for (; e < e1; e++) {
        int u0 = __ldg(&g_csrsrc[e]);
        float4 x0 = h4_to_f4(__ldg(&xlh[u0 * 32 + lane]));
        float p0 = logit_part(x0, xrv, attv);
        p0 += __shfl_xor_sync(0xffffffffu, p0, 8);
        p0 += __shfl_xor_sync(0xffffffffu, p0, 4);
        p0 += __shfl_xor_sync(0xffffffffu, p0, 2);
        p0 += __shfl_xor_sync(0xffffffffu, p0, 1);
        float a0 = __expf(p0 - m);
        z += a0;
        acc.x += a0 * x0.x; acc.y += a0 * x0.y;
        acc.z += a0 * x0.z; acc.w += a0 * x0.w;
    }

    float inv = 1.f / z;
    float4 r;
    r.x = acc.x * inv; r.y = acc.y * inv; r.z = acc.z * inv; r.w = acc.w * inv;
    // mean over heads: partner lane is lane^16
    r.x += __shfl_xor_sync(0xffffffffu, r.x, 16);
    r.y += __shfl_xor_sync(0xffffffffu, r.y, 16);
    r.z += __shfl_xor_sync(0xffffffffu, r.z, 16);
    r.w += __shfl_xor_sync(0xffffffffu, r.w, 16);
    if (lane < 16) {
        float4 b4 = __ldg(&((const float4*)bias)[lane]);
        float4 o;
        o.x = 0.5f * r.x + b4.x;
        o.y = 0.5f * r.y + b4.y;
        o.z = 0.5f * r.z + b4.z;
        o.w = 0.5f * r.w + b4.w;
        ((float4*)g_y)[v * 16 + lane] = o;
        int c = lane * 4;
        atomicAdd(&ssum[c + 0], o.x); atomicAdd(&ssq[c + 0], o.x * o.x);
        atomicAdd(&ssum[c + 1], o.y); atomicAdd(&ssq[c + 1], o.y * o.y);
        atomicAdd(&ssum[c + 2], o.z); atomicAdd(&ssq[c + 2], o.z * o.z);
        atomicAdd(&ssum[c + 3], o.w); atomicAdd(&ssq[c + 3], o.w * o.w);
    }
    __syncthreads();
    if (tid < 64) {
        atomicAdd(&g_sum[tid], ssum[tid]);
        atomicAdd(&g_sumsq[tid], ssq[tid]);
    }
}

// ---------------- finalize norm constants, re-zero stats ----------------
__global__ void k_fin(const float* __restrict__ gw, const float* __restrict__ gb,
                      const float* __restrict__ gm) {
    int c = threadIdx.x;  // 64
    const float invn = 1.f / (float)NN;
    float mu  = g_sum[c] * invn;
    float ex2 = g_sumsq[c] * invn;
    float gmv = __ldg(&gm[c]);
    float var = ex2 - gmv * (2.f - gmv) * mu * mu;
    float A = __ldg(&gw[c]) * rsqrtf(var + EPSV);
    g_nA[c] = A;
    g_nB[c] = __ldg(&gb[c]) - A * gmv * mu;
    g_sum[c] = 0.f;
    g_sumsq[c] = 0.f;
}

// ---------------- final apply (layer 3 output) ----------------
__global__ void k_apply3(float* __restrict__ xo) {
    int t = blockIdx.x * blockDim.x + threadIdx.x;
    int col = t & 63;
    xo[t] = fmaxf(g_y[t] * g_nA[col] + g_nB[col], 0.f);
}

// ---------------- launch (single stream, graph-capturable) ----------------
extern "C" void kernel_launch(void* const* d_in, const int* in_sizes, int n_in,
                              void* d_out, int out_size) {
    const float* x  = (const float*)d_in[0];
    const int*   ei = (const int*)d_in[1];
    const float *Wl[3], *Wr[3], *att[3], *bb[3], *gw[3], *gb[3], *gm[3];
    for (int i = 0; i < 3; i++) {
        int o = 2 + i * 7;
        Wl[i]  = (const float*)d_in[o + 0];
        Wr[i]  = (const float*)d_in[o + 1];
        att[i] = (const float*)d_in[o + 2];
        bb[i]  = (const float*)d_in[o + 3];
        gw[i]  = (const float*)d_in[o + 4];
        gb[i]  = (const float*)d_in[o + 5];
        gm[i]  = (const float*)d_in[o + 6];
    }
    const int* srcp = ei;
    const int* dstp = ei + EE;

    k_zero_all<<<(NN + 255) / 256, 256>>>();
    k_hist<<<(EE + 255) / 256, 256>>>(dstp);
    k_scan<<<1, 1024>>>();
    k_scatter<<<(EE + 255) / 256, 256>>>(srcp, dstp);
    k_gemm3<<<(NN * 32) / 256, 256>>>(x, Wl[0], Wr[0]);

    dim3 ggemm((NN + 63) / 64, 4);

    // layer 1
    k_agg<<<6250, 256>>>(att[0], bb[0]);
    k_fin<<<1, 64>>>(gw[0], gb[0], gm[0]);
    // layer 2 (layer-1 norm fused into GEMM input load)
    k_gemm64<<<ggemm, 256>>>(Wl[1], Wr[1]);
    k_agg<<<6250, 256>>>(att[1], bb[1]);
    k_fin<<<1, 64>>>(gw[1], gb[1], gm[1]);
    // layer 3
    k_gemm64<<<ggemm, 256>>>(Wl[2], Wr[2]);
    k_agg<<<6250, 256>>>(att[2], bb[2]);
    k_fin<<<1, 64>>>(gw[2], gb[2], gm[2]);
    k_apply3<<<(NN * 64) / 256, 256>>>((float*)d_out);
}

// round 10
// speedup vs baseline: 1.5548x; 1.5548x over previous
#include <cuda_runtime.h>

#define NN 50000
#define EE 800000
#define NEG 0.2f
#define EPSV 1e-5f

// ---- scratch (static __device__, no allocations) ----
__device__ float g_xl[NN * 128];
__device__ float g_xr[NN * 128];
__device__ float g_y[NN * 64];
__device__ int   g_cnt[NN];
__device__ int   g_wofs[NN];
__device__ int   g_rowptr[NN + 1];
__device__ int   g_csrsrc[EE];
__device__ float g_sum[64];
__device__ float g_sumsq[64];
__device__ float g_nA[64];
__device__ float g_nB[64];

// ---------------- CSR build ----------------
__global__ void k_zero_all() {
    int i = blockIdx.x * blockDim.x + threadIdx.x;
    if (i < NN) g_cnt[i] = 0;
    if (i < 64) { g_sum[i] = 0.f; g_sumsq[i] = 0.f; }
}

// stitched: blocks [0, 3125) do the dst histogram; blocks [3125, 9375) do layer-1 GEMM
__global__ void k_hist_gemm3(const int* __restrict__ dst,
                             const float* __restrict__ x,
                             const float* __restrict__ Wl,
                             const float* __restrict__ Wr) {
    if (blockIdx.x < 3125) {
        int e = blockIdx.x * 256 + threadIdx.x;
        if (e < EE) atomicAdd(&g_cnt[dst[e]], 1);
    } else {
        int t = (blockIdx.x - 3125) * 256 + threadIdx.x;
        int row = t >> 5, q = t & 31;
        if (row >= NN) return;
        float x0 = __ldg(&x[row * 3 + 0]);
        float x1 = __ldg(&x[row * 3 + 1]);
        float x2 = __ldg(&x[row * 3 + 2]);
        const float4* Wl4 = (const float4*)Wl;
        const float4* Wr4 = (const float4*)Wr;
        float4 a = __ldg(&Wl4[q]), b = __ldg(&Wl4[32 + q]), c = __ldg(&Wl4[64 + q]);
        float4 o;
        o.x = x0 * a.x + x1 * b.x + x2 * c.x;
        o.y = x0 * a.y + x1 * b.y + x2 * c.y;
        o.z = x0 * a.z + x1 * b.z + x2 * c.z;
        o.w = x0 * a.w + x1 * b.w + x2 * c.w;
        ((float4*)g_xl)[row * 32 + q] = o;
        a = __ldg(&Wr4[q]); b = __ldg(&Wr4[32 + q]); c = __ldg(&Wr4[64 + q]);
        o.x = x0 * a.x + x1 * b.x + x2 * c.x;
        o.y = x0 * a.y + x1 * b.y + x2 * c.y;
        o.z = x0 * a.z + x1 * b.z + x2 * c.z;
        o.w = x0 * a.w + x1 * b.w + x2 * c.w;
        ((float4*)g_xr)[row * 32 + q] = o;
    }
}

__global__ void k_scan() {
    __shared__ int sT[1024];
    int tid = threadIdx.x;
    const int CH = (NN + 1023) / 1024;
    int base = tid * CH;
    int s = 0;
    for (int i = 0; i < CH; i++) {
        int idx = base + i;
        s += (idx < NN) ? g_cnt[idx] : 0;
    }
    sT[tid] = s;
    __syncthreads();
    for (int off = 1; off < 1024; off <<= 1) {
        int v = (tid >= off) ? sT[tid - off] : 0;
        __syncthreads();
        sT[tid] += v;
        __syncthreads();
    }
    int run = (tid == 0) ? 0 : sT[tid - 1];
    for (int i = 0; i < CH; i++) {
        int idx = base + i;
        if (idx < NN) {
            g_rowptr[idx] = run;
            g_wofs[idx]   = run;
            run += g_cnt[idx];
        }
    }
    if (tid == 1023) g_rowptr[NN] = run;
}

__global__ void k_scatter(const int* __restrict__ src, const int* __restrict__ dst) {
    int e = blockIdx.x * blockDim.x + threadIdx.x;
    if (e < EE) {
        int p = atomicAdd(&g_wofs[dst[e]], 1);
        g_csrsrc[p] = src[e];
    }
}

// ---------------- layers 2/3 dual GEMM, 128-row tiles, fused GraphNorm+ReLU ----------------
// input row = relu(g_y * A + B);  [xl|xr](N,128) = in(N,64) @ W(64,128)
// grid (391, 4): by 0/1 -> Wl col-half 0/1 ; by 2/3 -> Wr col-half 0/1
__global__ void k_gemm64(const float* __restrict__ W_l, const float* __restrict__ W_r) {
    __shared__ float As[128][68];   // padded: conflict-free scalar reads
    __shared__ float Ws[64][64];
    int by = blockIdx.y;
    const float* W = (by < 2) ? W_l : W_r;
    float* Cp = (by < 2) ? g_xl : g_xr;
    int colbase = (by & 1) * 64;
    int row0 = blockIdx.x * 128;
    int tid = threadIdx.x;  // 256

    // A tile load (128 rows) with fused normalize + relu
    for (int i = tid; i < 128 * 16; i += 256) {
        int r = i >> 4, k4 = (i & 15) * 4;
        float4 v = make_float4(0.f, 0.f, 0.f, 0.f);
        if (row0 + r < NN) v = ((const float4*)g_y)[(row0 + r) * 16 + (k4 >> 2)];
        v.x = fmaxf(v.x * g_nA[k4 + 0] + g_nB[k4 + 0], 0.f);
        v.y = fmaxf(v.y * g_nA[k4 + 1] + g_nB[k4 + 1], 0.f);
        v.z = fmaxf(v.z * g_nA[k4 + 2] + g_nB[k4 + 2], 0.f);
        v.w = fmaxf(v.w * g_nA[k4 + 3] + g_nB[k4 + 3], 0.f);
        *(float4*)&As[r][k4] = v;
    }
    for (int i = tid; i < 64 * 16; i += 256) {
        int k = i >> 4, c4 = i & 15;
        *(float4*)&Ws[k][c4 * 4] = __ldg((const float4*)(W + k * 128 + colbase + c4 * 4));
    }
    __syncthreads();

    int tx = tid & 15, ty = tid >> 4;   // 8 rows x 4 cols per thread
    float acc[8][4];
#pragma unroll
    for (int i = 0; i < 8; i++)
#pragma unroll
        for (int j = 0; j < 4; j++) acc[i][j] = 0.f;

#pragma unroll 4
    for (int k = 0; k < 64; k++) {
        float4 wv = *(float4*)&Ws[k][tx * 4];
        float a[8];
#pragma unroll
        for (int i = 0; i < 8; i++) a[i] = As[ty * 8 + i][k];
#pragma unroll
        for (int i = 0; i < 8; i++) {
            acc[i][0] += a[i] * wv.x;
            acc[i][1] += a[i] * wv.y;
            acc[i][2] += a[i] * wv.z;
            acc[i][3] += a[i] * wv.w;
        }
    }
#pragma unroll
    for (int i = 0; i < 8; i++) {
        int r = row0 + ty * 8 + i;
        if (r < NN)
            *(float4*)&Cp[r * 128 + colbase + tx * 4] =
                make_float4(acc[i][0], acc[i][1], acc[i][2], acc[i][3]);
    }
}

// ---- per-edge logit partial: leakyrelu + att dot ----
__device__ __forceinline__ float logit_part(float4 xlv, float4 xrv, float4 attv) {
    float cx = xlv.x + xrv.x, cy = xlv.y + xrv.y, cz = xlv.z + xrv.z, cw = xlv.w + xrv.w;
    cx = fmaxf(cx, NEG * cx); cy = fmaxf(cy, NEG * cy);
    cz = fmaxf(cz, NEG * cz); cw = fmaxf(cw, NEG * cw);
    return cx * attv.x + cy * attv.y + cz * attv.z + cw * attv.w;
}

// ---------------- aggregation: one warp per node, 4 edges in flight ----------------
// lane l handles channels [l*4, l*4+4); lanes 0..15 = head 0, 16..31 = head 1.
__global__ void k_agg(const float* __restrict__ att, const float* __restrict__ bias) {
    __shared__ float ssum[64], ssq[64];
    int tid = threadIdx.x;
    if (tid < 64) { ssum[tid] = 0.f; ssq[tid] = 0.f; }
    __syncthreads();

    int v = (blockIdx.x * 256 + tid) >> 5;   // 6250 blocks * 8 warps = 50000 exactly
    int lane = tid & 31;
    const float4* xl4 = (const float4*)g_xl;
    float4 xrv  = ((const float4*)g_xr)[v * 32 + lane];
    float4 attv = __ldg(&((const float4*)att)[lane]);

    // self-loop: exp reference (a_self = 1)
    float4 xs = xl4[v * 32 + lane];
    float m = logit_part(xs, xrv, attv);
    m += __shfl_xor_sync(0xffffffffu, m, 8);
    m += __shfl_xor_sync(0xffffffffu, m, 4);
    m += __shfl_xor_sync(0xffffffffu, m, 2);
    m += __shfl_xor_sync(0xffffffffu, m, 1);

    float z = 1.f;
    float4 acc = xs;

    int e0 = __ldg(&g_rowptr[v]);
    int e1 = __ldg(&g_rowptr[v + 1]);
    int e = e0;
    for (; e + 4 <= e1; e += 4) {
        int u0 = __ldg(&g_csrsrc[e]);
        int u1 = __ldg(&g_csrsrc[e + 1]);
        int u2 = __ldg(&g_csrsrc[e + 2]);
        int u3 = __ldg(&g_csrsrc[e + 3]);
        float4 x0 = __ldg(&xl4[u0 * 32 + lane]);
        float4 x1 = __ldg(&xl4[u1 * 32 + lane]);
        float4 x2 = __ldg(&xl4[u2 * 32 + lane]);
        float4 x3 = __ldg(&xl4[u3 * 32 + lane]);
        float p0 = logit_part(x0, xrv, attv);
        float p1 = logit_part(x1, xrv, attv);
        float p2 = logit_part(x2, xrv, attv);
        float p3 = logit_part(x3, xrv, attv);
        p0 += __shfl_xor_sync(0xffffffffu, p0, 8);
        p1 += __shfl_xor_sync(0xffffffffu, p1, 8);
        p2 += __shfl_xor_sync(0xffffffffu, p2, 8);
        p3 += __shfl_xor_sync(0xffffffffu, p3, 8);
        p0 += __shfl_xor_sync(0xffffffffu, p0, 4);
        p1 += __shfl_xor_sync(0xffffffffu, p1, 4);
        p2 += __shfl_xor_sync(0xffffffffu, p2, 4);
        p3 += __shfl_xor_sync(0xffffffffu, p3, 4);
        p0 += __shfl_xor_sync(0xffffffffu, p0, 2);
        p1 += __shfl_xor_sync(0xffffffffu, p1, 2);
        p2 += __shfl_xor_sync(0xffffffffu, p2, 2);
        p3 += __shfl_xor_sync(0xffffffffu, p3, 2);
        p0 += __shfl_xor_sync(0xffffffffu, p0, 1);
        p1 += __shfl_xor_sync(0xffffffffu, p1, 1);
        p2 += __shfl_xor_sync(0xffffffffu, p2, 1);
        p3 += __shfl_xor_sync(0xffffffffu, p3, 1);
        float a0 = __expf(p0 - m);
        float a1 = __expf(p1 - m);
        float a2 = __expf(p2 - m);
        float a3 = __expf(p3 - m);
        z += (a0 + a1) + (a2 + a3);
        acc.x += a0 * x0.x + a1 * x1.x + a2 * x2.x + a3 * x3.x;
        acc.y += a0 * x0.y + a1 * x1.y + a2 * x2.y + a3 * x3.y;
        acc.z += a0 * x0.z + a1 * x1.z + a2 * x2.z + a3 * x3.z;
        acc.w += a0 * x0.w + a1 * x1.w + a2 * x2.w + a3 * x3.w;
    }
    for (; e < e1; e++) {
        int u0 = __ldg(&g_csrsrc[e]);
        float4 x0 = __ldg(&xl4[u0 * 32 + lane]);
        float p0 = logit_part(x0, xrv, attv);
        p0 += __shfl_xor_sync(0xffffffffu, p0, 8);
        p0 += __shfl_xor_sync(0xffffffffu, p0, 4);
        p0 += __shfl_xor_sync(0xffffffffu, p0, 2);
        p0 += __shfl_xor_sync(0xffffffffu, p0, 1);
        float a0 = __expf(p0 - m);
        z += a0;
        acc.x += a0 * x0.x; acc.y += a0 * x0.y;
        acc.z += a0 * x0.z; acc.w += a0 * x0.w;
    }

    float inv = 1.f / z;
    float4 r;
    r.x = acc.x * inv; r.y = acc.y * inv; r.z = acc.z * inv; r.w = acc.w * inv;
    // mean over heads: partner lane is lane^16
    r.x += __shfl_xor_sync(0xffffffffu, r.x, 16);
    r.y += __shfl_xor_sync(0xffffffffu, r.y, 16);
    r.z += __shfl_xor_sync(0xffffffffu, r.z, 16);
    r.w += __shfl_xor_sync(0xffffffffu, r.w, 16);
    if (lane < 16) {
        float4 b4 = __ldg(&((const float4*)bias)[lane]);
        float4 o;
        o.x = 0.5f * r.x + b4.x;
        o.y = 0.5f * r.y + b4.y;
        o.z = 0.5f * r.z + b4.z;
        o.w = 0.5f * r.w + b4.w;
        ((float4*)g_y)[v * 16 + lane] = o;
        int c = lane * 4;
        atomicAdd(&ssum[c + 0], o.x); atomicAdd(&ssq[c + 0], o.x * o.x);
        atomicAdd(&ssum[c + 1], o.y); atomicAdd(&ssq[c + 1], o.y * o.y);
        atomicAdd(&ssum[c + 2], o.z); atomicAdd(&ssq[c + 2], o.z * o.z);
        atomicAdd(&ssum[c + 3], o.w); atomicAdd(&ssq[c + 3], o.w * o.w);
    }
    __syncthreads();
    if (tid < 64) {
        atomicAdd(&g_sum[tid], ssum[tid]);
        atomicAdd(&g_sumsq[tid], ssq[tid]);
    }
}

// ---------------- finalize norm constants, re-zero stats ----------------
__global__ void k_fin(const float* __restrict__ gw, const float* __restrict__ gb,
                      const float* __restrict__ gm) {
    int c = threadIdx.x;  // 64
    const float invn = 1.f / (float)NN;
    float mu  = g_sum[c] * invn;
    float ex2 = g_sumsq[c] * invn;
    float gmv = __ldg(&gm[c]);
    float var = ex2 - gmv * (2.f - gmv) * mu * mu;
    float A = __ldg(&gw[c]) * rsqrtf(var + EPSV);
    g_nA[c] = A;
    g_nB[c] = __ldg(&gb[c]) - A * gmv * mu;
    g_sum[c] = 0.f;
    g_sumsq[c] = 0.f;
}

// ---------------- final apply (layer 3 output) ----------------
__global__ void k_apply3(float* __restrict__ xo) {
    int t = blockIdx.x * blockDim.x + threadIdx.x;
    int col = t & 63;
    xo[t] = fmaxf(g_y[t] * g_nA[col] + g_nB[col], 0.f);
}

// ---------------- launch (single stream, graph-capturable) ----------------
extern "C" void kernel_launch(void* const* d_in, const int* in_sizes, int n_in,
                              void* d_out, int out_size) {
    const float* x  = (const float*)d_in[0];
    const int*   ei = (const int*)d_in[1];
    const float *Wl[3], *Wr[3], *att[3], *bb[3], *gw[3], *gb[3], *gm[3];
    for (int i = 0; i < 3; i++) {
        int o = 2 + i * 7;
        Wl[i]  = (const float*)d_in[o + 0];
        Wr[i]  = (const float*)d_in[o + 1];
        att[i] = (const float*)d_in[o + 2];
        bb[i]  = (const float*)d_in[o + 3];
        gw[i]  = (const float*)d_in[o + 4];
        gb[i]  = (const float*)d_in[o + 5];
        gm[i]  = (const float*)d_in[o + 6];
    }
    const int* srcp = ei;
    const int* dstp = ei + EE;

    k_zero_all<<<(NN + 255) / 256, 256>>>();
    k_hist_gemm3<<<3125 + 6250, 256>>>(dstp, x, Wl[0], Wr[0]);   // hist ∥ layer-1 GEMM
    k_scan<<<1, 1024>>>();
    k_scatter<<<(EE + 255) / 256, 256>>>(srcp, dstp);

    dim3 ggemm((NN + 127) / 128, 4);

    // layer 1
    k_agg<<<6250, 256>>>(att[0], bb[0]);
    k_fin<<<1, 64>>>(gw[0], gb[0], gm[0]);
    // layer 2 (layer-1 norm fused into GEMM input load)
    k_gemm64<<<ggemm, 256>>>(Wl[1], Wr[1]);
    k_agg<<<6250, 256>>>(att[1], bb[1]);
    k_fin<<<1, 64>>>(gw[1], gb[1], gm[1]);
    // layer 3
    k_gemm64<<<ggemm, 256>>>(Wl[2], Wr[2]);
    k_agg<<<6250, 256>>>(att[2], bb[2]);
    k_fin<<<1, 64>>>(gw[2], gb[2], gm[2]);
    k_apply3<<<(NN * 64) / 256, 256>>>((float*)d_out);
}